// round 1
// baseline (speedup 1.0000x reference)
#include <cuda_runtime.h>
#include <cstdint>

#define N_NODES 100000
#define N_EDGES 2500000
#define N_GRAPHS 256
#define IN_F 6
#define HID 32
#define EMB 64

// ---------------- scratch (device globals; no allocations) ----------------
__device__ __align__(16) float g_deg[N_NODES];            // in-degree
__device__ __align__(16) float g_agg1[N_NODES * 8];       // layer-1 neighbor sums (6 used, padded to 8)
__device__ __align__(16) float g_h1[N_NODES * HID];       // relu(layer1) output
__device__ __align__(16) float g_agg2[N_NODES * HID];     // layer-2 neighbor sums
__device__ __align__(16) float g_gsum[N_GRAPHS * EMB];    // per-graph sums
__device__ __align__(16) float g_gcnt[N_GRAPHS];          // per-graph node counts

// ---------------- vector reductions (sm_90+: red.global.add.v4.f32) -------
__device__ __forceinline__ void red_add_v4(float* addr, float a, float b, float c, float d) {
    asm volatile("red.global.add.v4.f32 [%0], {%1,%2,%3,%4};"
                 :: "l"(addr), "f"(a), "f"(b), "f"(c), "f"(d) : "memory");
}
__device__ __forceinline__ void red_add_v2(float* addr, float a, float b) {
    asm volatile("red.global.add.v2.f32 [%0], {%1,%2};"
                 :: "l"(addr), "f"(a), "f"(b) : "memory");
}
__device__ __forceinline__ void red_add_f32(float* addr, float a) {
    asm volatile("red.global.add.f32 [%0], %1;"
                 :: "l"(addr), "f"(a) : "memory");
}

// ---------------- kernels ----------------

// Zero all accumulator scratch. Largest range: agg2 = 800000 float4.
__global__ void k_zero() {
    int i = blockIdx.x * blockDim.x + threadIdx.x;
    const float4 z = make_float4(0.f, 0.f, 0.f, 0.f);
    if (i < (N_NODES * HID) / 4)  reinterpret_cast<float4*>(g_agg2)[i] = z;
    if (i < (N_NODES * 8) / 4)    reinterpret_cast<float4*>(g_agg1)[i] = z;
    if (i < N_NODES / 4)          reinterpret_cast<float4*>(g_deg)[i]  = z;
    if (i < (N_GRAPHS * EMB) / 4) reinterpret_cast<float4*>(g_gsum)[i] = z;
    if (i < N_GRAPHS / 4)         reinterpret_cast<float4*>(g_gcnt)[i] = z;
}

// Pass 1: per-edge scatter of x[src] (6 floats) into agg1[dst] (+ degree count).
__global__ void k_edge1(const float* __restrict__ x,
                        const int* __restrict__ src,
                        const int* __restrict__ dst) {
    int e = blockIdx.x * blockDim.x + threadIdx.x;
    if (e >= N_EDGES) return;
    int s = src[e];
    int d = dst[e];
    const float* xr = x + (size_t)s * IN_F;      // 24B rows, 8B aligned
    float2 a = *reinterpret_cast<const float2*>(xr + 0);
    float2 b = *reinterpret_cast<const float2*>(xr + 2);
    float2 c = *reinterpret_cast<const float2*>(xr + 4);
    float* ar = g_agg1 + (size_t)d * 8;          // 32B rows, 16B aligned
    red_add_v4(ar,     a.x, a.y, b.x, b.y);
    red_add_v2(ar + 4, c.x, c.y);
    red_add_f32(g_deg + d, 1.0f);
}

// Layer 1 node update: h1 = relu(((agg1 + x) / (deg+1)) @ W1 + b1)
__global__ void k_node1(const float* __restrict__ x,
                        const float* __restrict__ W1,
                        const float* __restrict__ b1) {
    __shared__ float sW[IN_F * HID];
    __shared__ float sb[HID];
    for (int i = threadIdx.x; i < IN_F * HID; i += blockDim.x) sW[i] = W1[i];
    if (threadIdx.x < HID) sb[threadIdx.x] = b1[threadIdx.x];
    __syncthreads();

    int v = blockIdx.x * blockDim.x + threadIdx.x;
    if (v >= N_NODES) return;
    float inv = 1.0f / (g_deg[v] + 1.0f);
    const float* xr = x + (size_t)v * IN_F;
    const float* ar = g_agg1 + (size_t)v * 8;
    float nv[IN_F];
#pragma unroll
    for (int k = 0; k < IN_F; k++) nv[k] = (ar[k] + xr[k]) * inv;

    float* out = g_h1 + (size_t)v * HID;
#pragma unroll
    for (int j = 0; j < HID; j += 4) {
        float4 acc = make_float4(sb[j], sb[j+1], sb[j+2], sb[j+3]);
#pragma unroll
        for (int k = 0; k < IN_F; k++) {
            float4 w = *reinterpret_cast<const float4*>(sW + k * HID + j);
            acc.x += nv[k] * w.x; acc.y += nv[k] * w.y;
            acc.z += nv[k] * w.z; acc.w += nv[k] * w.w;
        }
        acc.x = fmaxf(acc.x, 0.f); acc.y = fmaxf(acc.y, 0.f);
        acc.z = fmaxf(acc.z, 0.f); acc.w = fmaxf(acc.w, 0.f);
        *reinterpret_cast<float4*>(out + j) = acc;
    }
}

// Pass 2: per-edge scatter of h1[src] (32 floats) into agg2[dst].
// 8 threads per edge, each moving one 16B chunk (coalesced 128B per edge).
__global__ void k_edge2(const int* __restrict__ src,
                        const int* __restrict__ dst) {
    int t = blockIdx.x * blockDim.x + threadIdx.x;
    if (t >= N_EDGES * 8) return;
    int e = t >> 3;
    int p = t & 7;
    int s = src[e];
    int d = dst[e];
    float4 h = *reinterpret_cast<const float4*>(g_h1 + (size_t)s * HID + p * 4);
    red_add_v4(g_agg2 + (size_t)d * HID + p * 4, h.x, h.y, h.z, h.w);
}

// Layer 2 node update + graph pooling accumulation:
// h2 = ((agg2 + h1) / (deg+1)) @ W2 + b2 ; gsum[gid] += h2 ; gcnt[gid] += 1
__global__ void k_node2(const int* __restrict__ gid,
                        const float* __restrict__ W2,
                        const float* __restrict__ b2) {
    __shared__ float sW[HID * EMB];   // 8KB
    __shared__ float sb[EMB];
    for (int i = threadIdx.x; i < HID * EMB; i += blockDim.x) sW[i] = W2[i];
    for (int i = threadIdx.x; i < EMB; i += blockDim.x) sb[i] = b2[i];
    __syncthreads();

    int v = blockIdx.x * blockDim.x + threadIdx.x;
    if (v >= N_NODES) return;
    float inv = 1.0f / (g_deg[v] + 1.0f);
    const float* h1r = g_h1 + (size_t)v * HID;
    const float* ar  = g_agg2 + (size_t)v * HID;
    float hn[HID];
#pragma unroll
    for (int k = 0; k < HID; k++) hn[k] = (ar[k] + h1r[k]) * inv;

    int g = gid[v];
    float* gs = g_gsum + (size_t)g * EMB;
#pragma unroll 2
    for (int j = 0; j < EMB; j += 4) {
        float4 acc = make_float4(sb[j], sb[j+1], sb[j+2], sb[j+3]);
#pragma unroll
        for (int k = 0; k < HID; k++) {
            float4 w = *reinterpret_cast<const float4*>(sW + k * EMB + j);
            acc.x += hn[k] * w.x; acc.y += hn[k] * w.y;
            acc.z += hn[k] * w.z; acc.w += hn[k] * w.w;
        }
        red_add_v4(gs + j, acc.x, acc.y, acc.z, acc.w);
    }
    red_add_f32(g_gcnt + g, 1.0f);
}

// Final: out[g][j] = gsum[g][j] / max(gcnt[g], 1)
__global__ void k_final(float* __restrict__ out) {
    int i = blockIdx.x * blockDim.x + threadIdx.x;
    if (i >= N_GRAPHS * EMB) return;
    int g = i / EMB;
    float c = g_gcnt[g];
    out[i] = g_gsum[i] / fmaxf(c, 1.0f);
}

// ---------------- launch ----------------
extern "C" void kernel_launch(void* const* d_in, const int* in_sizes, int n_in,
                              void* d_out, int out_size) {
    const float* x   = (const float*)d_in[0];
    const int*   src = (const int*)  d_in[1];
    const int*   dst = (const int*)  d_in[2];
    const int*   gid = (const int*)  d_in[3];
    const float* W1  = (const float*)d_in[4];
    const float* b1  = (const float*)d_in[5];
    const float* W2  = (const float*)d_in[6];
    const float* b2  = (const float*)d_in[7];
    float* out = (float*)d_out;

    const int TB = 256;
    {   // zero scratch: covers largest range (agg2 float4 count = 800000)
        int n = (N_NODES * HID) / 4;
        k_zero<<<(n + TB - 1) / TB, TB>>>();
    }
    k_edge1<<<(N_EDGES + TB - 1) / TB, TB>>>(x, src, dst);
    k_node1<<<(N_NODES + TB - 1) / TB, TB>>>(x, W1, b1);
    k_edge2<<<(N_EDGES * 8 + TB - 1) / TB, TB>>>(src, dst);
    k_node2<<<(N_NODES + TB - 1) / TB, TB>>>(gid, W2, b2);
    k_final<<<(N_GRAPHS * EMB + TB - 1) / TB, TB>>>(out);
}